// round 6
// baseline (speedup 1.0000x reference)
#include <cuda_runtime.h>
#include <cstdint>
#include <cstddef>

// Problem constants
#define NN 512
#define SD 256
#define ND 128
#define ED 16
#define CH 64               // i's per chunk in k_agg
#define NCH2 (NN / CH)      // 8 chunks

// ---------------- scratch (static device globals; no allocation) ----------------
__device__ float g_efd[NN * NN * 32];       // edge features, duplicated pairs: [j][i][t][2] (33.5 MB)
__device__ float g_n[NN * ND];              // node features after projector+LN
__device__ float g_n2[NN * ND];             // node features after MPN layer 1
__device__ float g_A[NN * ND];              // n @ mW_src
__device__ float g_B[NN * ND];              // n @ mW_dst + mb
__device__ float g_aggp[NCH2][NN * ND];     // partial aggregated messages (per i-chunk)
__device__ float g_P[NN * 64];              // n @ Wc1[:128]
__device__ float g_Q[NN * 64];              // n @ Wc1[128:] + bc1

// ---------------- packed f32x2 helpers (sm_103a FFMA2 path) ----------------
__device__ __forceinline__ unsigned long long pack2(float lo, float hi) {
    unsigned long long r;
    asm("mov.b64 %0, {%1, %2};" : "=l"(r) : "f"(lo), "f"(hi));
    return r;
}
__device__ __forceinline__ void unpack2(unsigned long long v, float& lo, float& hi) {
    asm("mov.b64 {%0, %1}, %2;" : "=f"(lo), "=f"(hi) : "l"(v));
}
__device__ __forceinline__ unsigned long long fma2(unsigned long long a,
                                                   unsigned long long b,
                                                   unsigned long long c) {
    unsigned long long d;
    asm("fma.rn.f32x2 %0, %1, %2, %3;" : "=l"(d) : "l"(a), "l"(b), "l"(c));
    return d;
}
__device__ __forceinline__ unsigned long long add2(unsigned long long a,
                                                   unsigned long long b) {
    unsigned long long d;
    asm("add.rn.f32x2 %0, %1, %2;" : "=l"(d) : "l"(a), "l"(b));
    return d;
}
__device__ __forceinline__ float tanh_fast(float x) {
    float y;
    asm("tanh.approx.f32 %0, %1;" : "=f"(y) : "f"(x));
    return y;
}

// ---------------- K1 (fused): spatial projector+LN  |  edge encoder ----------------
// blocks [0,256): node MLP, 2 nodes/block. blocks [256,768): edge encoder, j = bx-256.
__global__ __launch_bounds__(128) void k_pre(
    const float* __restrict__ X,
    const float* __restrict__ W1, const float* __restrict__ b1,
    const float* __restrict__ W2, const float* __restrict__ b2,
    const float* __restrict__ lng, const float* __restrict__ lnb,
    const float* __restrict__ pos,
    const float* __restrict__ We1, const float* __restrict__ be1,
    const float* __restrict__ We2, const float* __restrict__ be2)
{
    if (blockIdx.x < 256) {
        // ---- node MLP + LayerNorm, float4 weight loads, warp t-split ----
        constexpr int NB = 2;
        __shared__ float xs[NB][SD];
        __shared__ float h1[NB][ND];
        __shared__ float part[4][NB][ND];
        __shared__ float ssum[NB][4], ssq[NB][4];

        const int tid = threadIdx.x;
        const int tk = tid & 31;     // output group: k = 4*tk .. 4*tk+3
        const int tw = tid >> 5;     // t-quarter
        const int n0 = blockIdx.x * NB;

        for (int idx = tid; idx < NB * SD; idx += 128)
            xs[idx / SD][idx % SD] = X[n0 * SD + idx];
        __syncthreads();

        // GEMM1: [NB,SD] @ [SD,ND], each warp does 64 t's
        {
            float acc[NB][4];
#pragma unroll
            for (int nd = 0; nd < NB; nd++)
#pragma unroll
                for (int q = 0; q < 4; q++) acc[nd][q] = 0.f;
            const int tb = tw * 64;
#pragma unroll 8
            for (int tt = 0; tt < 64; tt++) {
                const int t = tb + tt;
                float4 w = *(const float4*)&W1[t * ND + 4 * tk];
#pragma unroll
                for (int nd = 0; nd < NB; nd++) {
                    float x = xs[nd][t];
                    acc[nd][0] += x * w.x;
                    acc[nd][1] += x * w.y;
                    acc[nd][2] += x * w.z;
                    acc[nd][3] += x * w.w;
                }
            }
#pragma unroll
            for (int nd = 0; nd < NB; nd++)
#pragma unroll
                for (int q = 0; q < 4; q++) part[tw][nd][4 * tk + q] = acc[nd][q];
        }
        __syncthreads();
        for (int idx = tid; idx < NB * ND; idx += 128) {
            int nd = idx >> 7, k = idx & 127;
            float v = part[0][nd][k] + part[1][nd][k] + part[2][nd][k] + part[3][nd][k];
            h1[nd][k] = fmaxf(v + b1[k], 0.f);
        }
        __syncthreads();

        // GEMM2: [NB,ND] @ [ND,ND], each warp does 32 t's
        {
            float acc[NB][4];
#pragma unroll
            for (int nd = 0; nd < NB; nd++)
#pragma unroll
                for (int q = 0; q < 4; q++) acc[nd][q] = 0.f;
            const int tb = tw * 32;
#pragma unroll 8
            for (int tt = 0; tt < 32; tt++) {
                const int t = tb + tt;
                float4 w = *(const float4*)&W2[t * ND + 4 * tk];
#pragma unroll
                for (int nd = 0; nd < NB; nd++) {
                    float x = h1[nd][t];
                    acc[nd][0] += x * w.x;
                    acc[nd][1] += x * w.y;
                    acc[nd][2] += x * w.z;
                    acc[nd][3] += x * w.w;
                }
            }
            __syncthreads();   // h1 reads done before part overwrite
#pragma unroll
            for (int nd = 0; nd < NB; nd++)
#pragma unroll
                for (int q = 0; q < 4; q++) part[tw][nd][4 * tk + q] = acc[nd][q];
        }
        __syncthreads();

        // LayerNorm, thread = k layout
        const int k = tid;
        float accv[NB];
#pragma unroll
        for (int nd = 0; nd < NB; nd++)
            accv[nd] = part[0][nd][k] + part[1][nd][k] + part[2][nd][k]
                     + part[3][nd][k] + b2[k];

        const int warp = k >> 5, lane = k & 31;
#pragma unroll
        for (int nd = 0; nd < NB; nd++) {
            float v = accv[nd], v2 = v * v;
            for (int o = 16; o > 0; o >>= 1) {
                v  += __shfl_xor_sync(0xffffffffu, v,  o);
                v2 += __shfl_xor_sync(0xffffffffu, v2, o);
            }
            if (lane == 0) { ssum[nd][warp] = v; ssq[nd][warp] = v2; }
        }
        __syncthreads();
        float gk = lng[k], bk = lnb[k];
#pragma unroll
        for (int nd = 0; nd < NB; nd++) {
            float s = ssum[nd][0] + ssum[nd][1] + ssum[nd][2] + ssum[nd][3];
            float q = ssq[nd][0] + ssq[nd][1] + ssq[nd][2] + ssq[nd][3];
            float mu = s * (1.0f / ND);
            float var = q * (1.0f / ND) - mu * mu;
            float r = rsqrtf(var + 1e-5f);
            g_n[(n0 + nd) * ND + k] = (accv[nd] - mu) * r * gk + bk;
        }
    } else {
        // ---- edge encoder: writes duplicated-pair layout ----
        __shared__ float w1s[64], b1s[16], w2s[256], b2s[16];
        const int tid = threadIdx.x;
        if (tid < 64) w1s[tid] = We1[tid];
        for (int idx = tid; idx < 256; idx += 128) w2s[idx] = We2[idx];
        if (tid < 16) { b1s[tid] = be1[tid]; b2s[tid] = be2[tid]; }

        const int j = blockIdx.x - 256;
        const float pjx = pos[j * 2], pjy = pos[j * 2 + 1];
        __syncthreads();

        for (int i = tid; i < NN; i += 128) {
            float4* o4 = (float4*)&g_efd[((size_t)j * NN + i) * 32];
            if (i == j) {
                float4 z = make_float4(0.f, 0.f, 0.f, 0.f);
#pragma unroll
                for (int r = 0; r < 8; r++) o4[r] = z;
                continue;
            }
            const float pix = pos[i * 2], piy = pos[i * 2 + 1];
            const float dx = pjx - pix, dy = pjy - piy;
            const float dist = sqrtf(dx * dx + dy * dy);
            const float ang = atan2f(dy, dx);
            float h[16];
#pragma unroll
            for (int u = 0; u < 16; u++) {
                float a = pix * w1s[u] + piy * w1s[16 + u] + dist * w1s[32 + u]
                        + ang * w1s[48 + u] + b1s[u];
                h[u] = fmaxf(a, 0.f);
            }
            float o[16];
#pragma unroll
            for (int v = 0; v < 16; v++) {
                float a = b2s[v];
#pragma unroll
                for (int u = 0; u < 16; u++) a += h[u] * w2s[u * 16 + v];
                o[v] = tanh_fast(a);
            }
#pragma unroll
            for (int r = 0; r < 8; r++)
                o4[r] = make_float4(o[2 * r], o[2 * r], o[2 * r + 1], o[2 * r + 1]);
        }
    }
}

// ---------------- K3: A = n@mW_src,  B = n@mW_dst + mb (float4 loads, warp t-split) ----
__global__ __launch_bounds__(128) void k_ab(
    const float* __restrict__ nin,
    const float* __restrict__ mW, const float* __restrict__ mb)
{
    constexpr int NB = 2;
    __shared__ float xs[NB][ND];
    __shared__ float partA[4][NB][ND];
    __shared__ float partB[4][NB][ND];
    const int tid = threadIdx.x;
    const int tk = tid & 31;
    const int tw = tid >> 5;
    const int n0 = blockIdx.x * NB;

    for (int idx = tid; idx < NB * ND; idx += 128)
        xs[idx >> 7][idx & 127] = nin[n0 * ND + idx];
    __syncthreads();

    float accA[NB][4], accB[NB][4];
#pragma unroll
    for (int nd = 0; nd < NB; nd++)
#pragma unroll
        for (int q = 0; q < 4; q++) { accA[nd][q] = 0.f; accB[nd][q] = 0.f; }

    const int tb = tw * 32;
#pragma unroll 4
    for (int tt = 0; tt < 32; tt++) {
        const int t = tb + tt;
        float4 wA = *(const float4*)&mW[t * ND + 4 * tk];
        float4 wB = *(const float4*)&mW[(ND + t) * ND + 4 * tk];
#pragma unroll
        for (int nd = 0; nd < NB; nd++) {
            float x = xs[nd][t];
            accA[nd][0] += x * wA.x;  accA[nd][1] += x * wA.y;
            accA[nd][2] += x * wA.z;  accA[nd][3] += x * wA.w;
            accB[nd][0] += x * wB.x;  accB[nd][1] += x * wB.y;
            accB[nd][2] += x * wB.z;  accB[nd][3] += x * wB.w;
        }
    }
#pragma unroll
    for (int nd = 0; nd < NB; nd++)
#pragma unroll
        for (int q = 0; q < 4; q++) {
            partA[tw][nd][4 * tk + q] = accA[nd][q];
            partB[tw][nd][4 * tk + q] = accB[nd][q];
        }
    __syncthreads();

    for (int idx = tid; idx < NB * ND; idx += 128) {
        int nd = idx >> 7, k = idx & 127;
        float a = partA[0][nd][k] + partA[1][nd][k] + partA[2][nd][k] + partA[3][nd][k];
        float b = partB[0][nd][k] + partB[1][nd][k] + partB[2][nd][k] + partB[3][nd][k];
        g_A[(n0 + nd) * ND + k] = a;
        g_B[(n0 + nd) * ND + k] = b + mb[k];
    }
}

// ---------------- K4: fused ef-matvec + relu + segment-sum (partial) ----------------
// block = 128 threads = 4 warps, each warp one dst j; thread covers 4 features:
// (2*lane, 2*lane+1) and (64+2*lane, 65+2*lane), each as one packed f32x2 chain.
// grid = (128 j-quads, NCH2 i-chunks of CH=64 i's). ef read directly from gmem
// (uniform-address LDG.128 broadcasts). Each i = 128 B = 8 ulonglong2.
__global__ __launch_bounds__(128) void k_agg(const float* __restrict__ mW)
{
    const int grp  = threadIdx.x >> 5;
    const int lane = threadIdx.x & 31;
    const int j  = blockIdx.x * 4 + grp;
    const int i0 = blockIdx.y * CH;
    const int kA = 2 * lane;
    const int kB = 64 + 2 * lane;

    unsigned long long WA[ED], WB[ED];
#pragma unroll
    for (int t = 0; t < ED; t++) {
        float2 wa = *(const float2*)&mW[(2 * ND + t) * ND + kA];
        float2 wb = *(const float2*)&mW[(2 * ND + t) * ND + kB];
        WA[t] = pack2(wa.x, wa.y);
        WB[t] = pack2(wb.x, wb.y);
    }
    float2 ba = *(const float2*)&g_B[j * ND + kA];
    float2 bb = *(const float2*)&g_B[j * ND + kB];
    const unsigned long long BA = pack2(ba.x, ba.y);
    const unsigned long long BB = pack2(bb.x, bb.y);

    const ulonglong2* efbase = (const ulonglong2*)&g_efd[((size_t)j * NN + i0) * 32];

    float a0 = 0.f, a1 = 0.f, a2 = 0.f, a3 = 0.f;
#pragma unroll 2
    for (int ii = 0; ii < CH; ii++) {
        const int i = i0 + ii;
        float2 aA = *(const float2*)&g_A[i * ND + kA];
        float2 aB = *(const float2*)&g_A[i * ND + kB];
        const ulonglong2* ep = efbase + ii * 8;   // 128 B per i
        ulonglong2 q0 = ep[0], q1 = ep[1], q2 = ep[2], q3 = ep[3];

        unsigned long long eA0 = BA, eA1 = pack2(aA.x, aA.y);
        unsigned long long eB0 = BB, eB1 = pack2(aB.x, aB.y);
        eA0 = fma2(q0.x, WA[0],  eA0);  eA1 = fma2(q0.y, WA[1],  eA1);
        eB0 = fma2(q0.x, WB[0],  eB0);  eB1 = fma2(q0.y, WB[1],  eB1);
        eA0 = fma2(q1.x, WA[2],  eA0);  eA1 = fma2(q1.y, WA[3],  eA1);
        eB0 = fma2(q1.x, WB[2],  eB0);  eB1 = fma2(q1.y, WB[3],  eB1);
        eA0 = fma2(q2.x, WA[4],  eA0);  eA1 = fma2(q2.y, WA[5],  eA1);
        eB0 = fma2(q2.x, WB[4],  eB0);  eB1 = fma2(q2.y, WB[5],  eB1);
        eA0 = fma2(q3.x, WA[6],  eA0);  eA1 = fma2(q3.y, WA[7],  eA1);
        eB0 = fma2(q3.x, WB[6],  eB0);  eB1 = fma2(q3.y, WB[7],  eB1);
        ulonglong2 q4 = ep[4], q5 = ep[5], q6 = ep[6], q7 = ep[7];
        eA0 = fma2(q4.x, WA[8],  eA0);  eA1 = fma2(q4.y, WA[9],  eA1);
        eB0 = fma2(q4.x, WB[8],  eB0);  eB1 = fma2(q4.y, WB[9],  eB1);
        eA0 = fma2(q5.x, WA[10], eA0);  eA1 = fma2(q5.y, WA[11], eA1);
        eB0 = fma2(q5.x, WB[10], eB0);  eB1 = fma2(q5.y, WB[11], eB1);
        eA0 = fma2(q6.x, WA[12], eA0);  eA1 = fma2(q6.y, WA[13], eA1);
        eB0 = fma2(q6.x, WB[12], eB0);  eB1 = fma2(q6.y, WB[13], eB1);
        eA0 = fma2(q7.x, WA[14], eA0);  eA1 = fma2(q7.y, WA[15], eA1);
        eB0 = fma2(q7.x, WB[14], eB0);  eB1 = fma2(q7.y, WB[15], eB1);

        unsigned long long vA = add2(eA0, eA1);
        unsigned long long vB = add2(eB0, eB1);
        float v0, v1, v2, v3;
        unpack2(vA, v0, v1);
        unpack2(vB, v2, v3);
        if (i != j) {
            a0 += fmaxf(v0, 0.f);
            a1 += fmaxf(v1, 0.f);
            a2 += fmaxf(v2, 0.f);
            a3 += fmaxf(v3, 0.f);
        }
    }

    float* dst = &g_aggp[blockIdx.y][j * ND];
    *(float2*)&dst[kA] = make_float2(a0, a1);
    *(float2*)&dst[kB] = make_float2(a2, a3);
}

// ---------------- K5: update MLP  n_out = relu([n, sum(aggp)] @ uW + ub) ----------------
// float4 weight loads, warp t-split over 2*ND=256.
__global__ __launch_bounds__(128) void k_upd(
    const float* __restrict__ nin,
    const float* __restrict__ uW, const float* __restrict__ ub,
    float* __restrict__ nout)
{
    constexpr int NB = 2;
    __shared__ float xs[NB][2 * ND];
    __shared__ float part[4][NB][ND];
    const int tid = threadIdx.x;
    const int tk = tid & 31;
    const int tw = tid >> 5;
    const int n0 = blockIdx.x * NB;

    for (int idx = tid; idx < NB * ND; idx += 128) {
        int nd = idx >> 7, t = idx & 127;
        int off = (n0 + nd) * ND + t;
        float s = g_aggp[0][off];
#pragma unroll
        for (int c = 1; c < NCH2; c++) s += g_aggp[c][off];
        xs[nd][t]      = nin[off];
        xs[nd][ND + t] = s;
    }
    __syncthreads();

    float acc[NB][4];
#pragma unroll
    for (int nd = 0; nd < NB; nd++)
#pragma unroll
        for (int q = 0; q < 4; q++) acc[nd][q] = 0.f;

    const int tb = tw * 64;
#pragma unroll 8
    for (int tt = 0; tt < 64; tt++) {
        const int t = tb + tt;
        float4 w = *(const float4*)&uW[t * ND + 4 * tk];
#pragma unroll
        for (int nd = 0; nd < NB; nd++) {
            float x = xs[nd][t];
            acc[nd][0] += x * w.x;
            acc[nd][1] += x * w.y;
            acc[nd][2] += x * w.z;
            acc[nd][3] += x * w.w;
        }
    }
#pragma unroll
    for (int nd = 0; nd < NB; nd++)
#pragma unroll
        for (int q = 0; q < 4; q++) part[tw][nd][4 * tk + q] = acc[nd][q];
    __syncthreads();

    for (int idx = tid; idx < NB * ND; idx += 128) {
        int nd = idx >> 7, k = idx & 127;
        float v = part[0][nd][k] + part[1][nd][k] + part[2][nd][k] + part[3][nd][k];
        nout[(n0 + nd) * ND + k] = fmaxf(v + ub[k], 0.f);
    }
}

// ---------------- K6: P = n@Wc1[:128],  Q = n@Wc1[128:] + bc1 (float4 loads) ----------
// 128 threads: halves over P/Q; within half: 16 k-groups x 4 t-quarters. NB=4.
__global__ __launch_bounds__(128) void k_pq(
    const float* __restrict__ nin,
    const float* __restrict__ Wc1, const float* __restrict__ bc1)
{
    constexpr int NB = 4;
    __shared__ float xs[NB][ND];
    __shared__ float part[2][4][NB][64];   // [half][tw][node][k] = 8 KB
    const int tid = threadIdx.x;
    const int half = tid >> 6;
    const int t64 = tid & 63;
    const int tk = t64 & 15;       // k = 4*tk .. 4*tk+3 (of 64)
    const int tw = t64 >> 4;       // t-quarter of 128
    const int n0 = blockIdx.x * NB;

    for (int idx = tid; idx < NB * ND; idx += 128)
        xs[idx >> 7][idx & 127] = nin[n0 * ND + idx];
    __syncthreads();

    float acc[NB][4];
#pragma unroll
    for (int nd = 0; nd < NB; nd++)
#pragma unroll
        for (int q = 0; q < 4; q++) acc[nd][q] = 0.f;

    const float* Wcol = &Wc1[half * ND * 64];
    const int tb = tw * 32;
#pragma unroll 8
    for (int tt = 0; tt < 32; tt++) {
        const int t = tb + tt;
        float4 w = *(const float4*)&Wcol[t * 64 + 4 * tk];
#pragma unroll
        for (int nd = 0; nd < NB; nd++) {
            float x = xs[nd][t];
            acc[nd][0] += x * w.x;
            acc[nd][1] += x * w.y;
            acc[nd][2] += x * w.z;
            acc[nd][3] += x * w.w;
        }
    }
#pragma unroll
    for (int nd = 0; nd < NB; nd++)
#pragma unroll
        for (int q = 0; q < 4; q++) part[half][tw][nd][4 * tk + q] = acc[nd][q];
    __syncthreads();

    for (int idx = tid; idx < 2 * NB * 64; idx += 128) {
        int h2 = idx >> 8, rest = idx & 255;
        int nd = rest >> 6, k = rest & 63;
        float v = part[h2][0][nd][k] + part[h2][1][nd][k]
                + part[h2][2][nd][k] + part[h2][3][nd][k];
        if (h2) g_Q[(n0 + nd) * 64 + k] = v + bc1[k];
        else    g_P[(n0 + nd) * 64 + k] = v;
    }
}

// ---------------- K7: pairwise scores (relu(P_i+Q_j) @ Wc2 -> sigmoid) ----------------
__global__ __launch_bounds__(256) void k_scores(
    const float* __restrict__ Wc2, const float* __restrict__ bc2,
    float* __restrict__ out)
{
    __shared__ float Ps[16][65], Qs[16][65], ws[64];
    const int tid = threadIdx.x;
    const int tx = tid & 15, ty = tid >> 4;
    const int j0 = blockIdx.x * 16, i0 = blockIdx.y * 16;

    for (int idx = tid; idx < 16 * 64; idx += 256) {
        int r = idx >> 6, c = idx & 63;
        Ps[r][c] = g_P[(i0 + r) * 64 + c];
        Qs[r][c] = g_Q[(j0 + r) * 64 + c];
    }
    if (tid < 64) ws[tid] = Wc2[tid];
    __syncthreads();

    float acc = 0.f;
#pragma unroll 8
    for (int t = 0; t < 64; t++)
        acc += fmaxf(Ps[ty][t] + Qs[tx][t], 0.f) * ws[t];
    acc += bc2[0];
    float s = 1.f / (1.f + expf(-acc));
    const int i = i0 + ty, j = j0 + tx;
    out[i * NN + j] = (i == j) ? 0.f : s;
}

// ---------------- launch ----------------
extern "C" void kernel_launch(void* const* d_in, const int* in_sizes, int n_in,
                              void* d_out, int out_size)
{
    const float* X   = (const float*)d_in[0];
    const float* pos = (const float*)d_in[1];
    const float* W1  = (const float*)d_in[2];
    const float* b1  = (const float*)d_in[3];
    const float* W2  = (const float*)d_in[4];
    const float* b2  = (const float*)d_in[5];
    const float* lng = (const float*)d_in[6];
    const float* lnb = (const float*)d_in[7];
    const float* We1 = (const float*)d_in[8];
    const float* be1 = (const float*)d_in[9];
    const float* We2 = (const float*)d_in[10];
    const float* be2 = (const float*)d_in[11];
    const float* mW1 = (const float*)d_in[12];
    const float* mb1 = (const float*)d_in[13];
    const float* uW1 = (const float*)d_in[14];
    const float* ub1 = (const float*)d_in[15];
    const float* mW2 = (const float*)d_in[16];
    const float* mb2 = (const float*)d_in[17];
    const float* uW2 = (const float*)d_in[18];
    const float* ub2 = (const float*)d_in[19];
    const float* Wc1 = (const float*)d_in[20];
    const float* bc1 = (const float*)d_in[21];
    const float* Wc2 = (const float*)d_in[22];
    const float* bc2 = (const float*)d_in[23];

    float* out   = (float*)d_out;
    float* out_n = out;             // [512*128] node features
    float* out_s = out + NN * ND;   // [512*512] scores

    float *pN = nullptr, *pN2 = nullptr;
    cudaGetSymbolAddress((void**)&pN,  g_n);
    cudaGetSymbolAddress((void**)&pN2, g_n2);

    // fused: node projector+LN (blocks 0..255) + edge encoder (blocks 256..767)
    k_pre<<<768, 128>>>(X, W1, b1, W2, b2, lng, lnb,
                        pos, We1, be1, We2, be2);

    // MPN layer 1
    k_ab<<<256, 128>>>(pN, mW1, mb1);
    k_agg<<<dim3(128, NCH2), 128>>>(mW1);
    k_upd<<<256, 128>>>(pN, uW1, ub1, pN2);

    // MPN layer 2 (final node features written straight into d_out)
    k_ab<<<256, 128>>>(pN2, mW2, mb2);
    k_agg<<<dim3(128, NCH2), 128>>>(mW2);
    k_upd<<<256, 128>>>(pN2, uW2, ub2, out_n);

    // classifier
    k_pq<<<128, 128>>>(out_n, Wc1, bc1);
    k_scores<<<dim3(32, 32), 256>>>(Wc2, bc2, out_s);
}

// round 7
// speedup vs baseline: 1.7161x; 1.7161x over previous
#include <cuda_runtime.h>
#include <cstdint>
#include <cstddef>

// Problem constants
#define NN 512
#define SD 256
#define ND 128
#define ED 16
#define CH 64               // i's per chunk in k_agg
#define NCH2 (NN / CH)      // 8 chunks

// ---------------- scratch (static device globals; no allocation) ----------------
__device__ float g_efd[NN * NN * 32];       // edge features, duplicated pairs: [j][i][t][2] (33.5 MB)
__device__ float g_n[NN * ND];              // node features after projector+LN
__device__ float g_n2[NN * ND];             // node features after MPN layer 1
__device__ float g_A[NN * ND];              // n @ mW_src
__device__ float g_B[NN * ND];              // n @ mW_dst + mb
__device__ float g_aggp[NCH2][NN * ND];     // partial aggregated messages (per i-chunk)
__device__ float g_P[NN * 64];              // n @ Wc1[:128]
__device__ float g_Q[NN * 64];              // n @ Wc1[128:] + bc1

// ---------------- packed f32x2 helpers (sm_103a FFMA2 path) ----------------
__device__ __forceinline__ unsigned long long pack2(float lo, float hi) {
    unsigned long long r;
    asm("mov.b64 %0, {%1, %2};" : "=l"(r) : "f"(lo), "f"(hi));
    return r;
}
__device__ __forceinline__ void unpack2(unsigned long long v, float& lo, float& hi) {
    asm("mov.b64 {%0, %1}, %2;" : "=f"(lo), "=f"(hi) : "l"(v));
}
__device__ __forceinline__ unsigned long long fma2(unsigned long long a,
                                                   unsigned long long b,
                                                   unsigned long long c) {
    unsigned long long d;
    asm("fma.rn.f32x2 %0, %1, %2, %3;" : "=l"(d) : "l"(a), "l"(b), "l"(c));
    return d;
}
__device__ __forceinline__ unsigned long long add2(unsigned long long a,
                                                   unsigned long long b) {
    unsigned long long d;
    asm("add.rn.f32x2 %0, %1, %2;" : "=l"(d) : "l"(a), "l"(b));
    return d;
}
__device__ __forceinline__ float tanh_fast(float x) {
    float y;
    asm("tanh.approx.f32 %0, %1;" : "=f"(y) : "f"(x));
    return y;
}

// ---------------- K1 (fused): spatial projector+LN  |  edge encoder ----------------
// 256 threads. blocks [0,256): node MLP, 2 nodes/block, thread = (node, feature).
// blocks [256,768): edge encoder, j = bx-256.
__global__ __launch_bounds__(256) void k_pre(
    const float* __restrict__ X,
    const float* __restrict__ W1, const float* __restrict__ b1,
    const float* __restrict__ W2, const float* __restrict__ b2,
    const float* __restrict__ lng, const float* __restrict__ lnb,
    const float* __restrict__ pos,
    const float* __restrict__ We1, const float* __restrict__ be1,
    const float* __restrict__ We2, const float* __restrict__ be2)
{
    const int tid = threadIdx.x;
    if (blockIdx.x < 256) {
        // ---- node MLP + LayerNorm; thread = (nd, k) ----
        __shared__ float xs[2][SD];
        __shared__ float h1[2][ND];
        __shared__ float ssum[2][4], ssq[2][4];

        const int nd = tid >> 7;          // node within block
        const int k  = tid & 127;         // feature
        const int n0 = blockIdx.x * 2;

        for (int idx = tid; idx < 2 * SD; idx += 256)
            xs[idx >> 8][idx & 255] = X[n0 * SD + idx];
        __syncthreads();

        float acc = 0.f;
        for (int t = 0; t < SD; t++)
            acc += xs[nd][t] * W1[t * ND + k];
        h1[nd][k] = fmaxf(acc + b1[k], 0.f);
        __syncthreads();

        acc = 0.f;
        for (int t = 0; t < ND; t++)
            acc += h1[nd][t] * W2[t * ND + k];
        acc += b2[k];

        // LayerNorm over features per node; node nd occupies warps nd*4..nd*4+3
        const int w4 = (tid >> 5) & 3, lane = tid & 31;
        {
            float v = acc, v2 = v * v;
            for (int o = 16; o > 0; o >>= 1) {
                v  += __shfl_xor_sync(0xffffffffu, v,  o);
                v2 += __shfl_xor_sync(0xffffffffu, v2, o);
            }
            if (lane == 0) { ssum[nd][w4] = v; ssq[nd][w4] = v2; }
        }
        __syncthreads();
        float s = ssum[nd][0] + ssum[nd][1] + ssum[nd][2] + ssum[nd][3];
        float q = ssq[nd][0] + ssq[nd][1] + ssq[nd][2] + ssq[nd][3];
        float mu = s * (1.0f / ND);
        float var = q * (1.0f / ND) - mu * mu;
        float r = rsqrtf(var + 1e-5f);
        g_n[(n0 + nd) * ND + k] = (acc - mu) * r * lng[k] + lnb[k];
    } else {
        // ---- edge encoder: writes duplicated-pair layout ----
        __shared__ float w1s[64], b1s[16], w2s[256], b2s[16];
        if (tid < 64) w1s[tid] = We1[tid];
        for (int idx = tid; idx < 256; idx += 256) w2s[idx] = We2[idx];
        if (tid < 16) { b1s[tid] = be1[tid]; b2s[tid] = be2[tid]; }

        const int j = blockIdx.x - 256;
        const float pjx = pos[j * 2], pjy = pos[j * 2 + 1];
        __syncthreads();

        for (int i = tid; i < NN; i += 256) {
            float4* o4 = (float4*)&g_efd[((size_t)j * NN + i) * 32];
            if (i == j) {
                float4 z = make_float4(0.f, 0.f, 0.f, 0.f);
#pragma unroll
                for (int r = 0; r < 8; r++) o4[r] = z;
                continue;
            }
            const float pix = pos[i * 2], piy = pos[i * 2 + 1];
            const float dx = pjx - pix, dy = pjy - piy;
            const float dist = sqrtf(dx * dx + dy * dy);
            const float ang = atan2f(dy, dx);
            float h[16];
#pragma unroll
            for (int u = 0; u < 16; u++) {
                float a = pix * w1s[u] + piy * w1s[16 + u] + dist * w1s[32 + u]
                        + ang * w1s[48 + u] + b1s[u];
                h[u] = fmaxf(a, 0.f);
            }
            float o[16];
#pragma unroll
            for (int v = 0; v < 16; v++) {
                float a = b2s[v];
#pragma unroll
                for (int u = 0; u < 16; u++) a += h[u] * w2s[u * 16 + v];
                o[v] = tanh_fast(a);
            }
#pragma unroll
            for (int r = 0; r < 8; r++)
                o4[r] = make_float4(o[2 * r], o[2 * r], o[2 * r + 1], o[2 * r + 1]);
        }
    }
}

// ---------------- K3: A = n@mW_src,  B = n@mW_dst + mb ----------------
// 256 threads, 2 nodes/block, thread = (nd, k).
__global__ __launch_bounds__(256) void k_ab(
    const float* __restrict__ nin,
    const float* __restrict__ mW, const float* __restrict__ mb)
{
    __shared__ float xs[2][ND];
    const int tid = threadIdx.x;
    const int nd = tid >> 7;
    const int k  = tid & 127;
    const int n0 = blockIdx.x * 2;

    xs[nd][k] = nin[n0 * ND + tid];
    __syncthreads();

    float a = 0.f, b = 0.f;
    for (int t = 0; t < ND; t++) {
        float x = xs[nd][t];
        a += x * mW[t * ND + k];
        b += x * mW[(ND + t) * ND + k];
    }
    g_A[(n0 + nd) * ND + k] = a;
    g_B[(n0 + nd) * ND + k] = b + mb[k];
}

// ---------------- K4: fused ef-matvec + relu + segment-sum (partial) ----------------
// EXACT R3 version (proven). block = 128 threads = 4 warps, each warp one dst j;
// thread covers 4 features as two packed f32x2 chains. grid = (128, NCH2).
__global__ __launch_bounds__(128) void k_agg(const float* __restrict__ mW)
{
    __shared__ __align__(16) float efs[4][CH * 32];   // 4 warps * 8 KB = 32 KB

    const int grp  = threadIdx.x >> 5;
    const int lane = threadIdx.x & 31;
    const int j  = blockIdx.x * 4 + grp;
    const int i0 = blockIdx.y * CH;
    const int kA = 2 * lane;
    const int kB = 64 + 2 * lane;

    unsigned long long WA[ED], WB[ED];
#pragma unroll
    for (int t = 0; t < ED; t++) {
        float2 wa = *(const float2*)&mW[(2 * ND + t) * ND + kA];
        float2 wb = *(const float2*)&mW[(2 * ND + t) * ND + kB];
        WA[t] = pack2(wa.x, wa.y);
        WB[t] = pack2(wb.x, wb.y);
    }
    float2 ba = *(const float2*)&g_B[j * ND + kA];
    float2 bb = *(const float2*)&g_B[j * ND + kB];
    const unsigned long long BA = pack2(ba.x, ba.y);
    const unsigned long long BB = pack2(bb.x, bb.y);

    // stage this warp's CH i's of duplicated ef (8 KB) — coalesced copy
    {
        const float4* src = (const float4*)&g_efd[((size_t)j * NN + i0) * 32];
        float4* dst = (float4*)efs[grp];
#pragma unroll
        for (int r = 0; r < 16; r++)
            dst[lane + 32 * r] = src[lane + 32 * r];
    }
    __syncthreads();

    float a0 = 0.f, a1 = 0.f, a2 = 0.f, a3 = 0.f;
#pragma unroll 2
    for (int ii = 0; ii < CH; ii++) {
        const int i = i0 + ii;
        float2 aA = *(const float2*)&g_A[i * ND + kA];
        float2 aB = *(const float2*)&g_A[i * ND + kB];
        const ulonglong2* ep = (const ulonglong2*)&efs[grp][ii * 32];
        ulonglong2 q0 = ep[0], q1 = ep[1], q2 = ep[2], q3 = ep[3];
        ulonglong2 q4 = ep[4], q5 = ep[5], q6 = ep[6], q7 = ep[7];

        unsigned long long eA0 = BA, eA1 = pack2(aA.x, aA.y);
        unsigned long long eB0 = BB, eB1 = pack2(aB.x, aB.y);
        eA0 = fma2(q0.x, WA[0],  eA0);  eA1 = fma2(q0.y, WA[1],  eA1);
        eB0 = fma2(q0.x, WB[0],  eB0);  eB1 = fma2(q0.y, WB[1],  eB1);
        eA0 = fma2(q1.x, WA[2],  eA0);  eA1 = fma2(q1.y, WA[3],  eA1);
        eB0 = fma2(q1.x, WB[2],  eB0);  eB1 = fma2(q1.y, WB[3],  eB1);
        eA0 = fma2(q2.x, WA[4],  eA0);  eA1 = fma2(q2.y, WA[5],  eA1);
        eB0 = fma2(q2.x, WB[4],  eB0);  eB1 = fma2(q2.y, WB[5],  eB1);
        eA0 = fma2(q3.x, WA[6],  eA0);  eA1 = fma2(q3.y, WA[7],  eA1);
        eB0 = fma2(q3.x, WB[6],  eB0);  eB1 = fma2(q3.y, WB[7],  eB1);
        eA0 = fma2(q4.x, WA[8],  eA0);  eA1 = fma2(q4.y, WA[9],  eA1);
        eB0 = fma2(q4.x, WB[8],  eB0);  eB1 = fma2(q4.y, WB[9],  eB1);
        eA0 = fma2(q5.x, WA[10], eA0);  eA1 = fma2(q5.y, WA[11], eA1);
        eB0 = fma2(q5.x, WB[10], eB0);  eB1 = fma2(q5.y, WB[11], eB1);
        eA0 = fma2(q6.x, WA[12], eA0);  eA1 = fma2(q6.y, WA[13], eA1);
        eB0 = fma2(q6.x, WB[12], eB0);  eB1 = fma2(q6.y, WB[13], eB1);
        eA0 = fma2(q7.x, WA[14], eA0);  eA1 = fma2(q7.y, WA[15], eA1);
        eB0 = fma2(q7.x, WB[14], eB0);  eB1 = fma2(q7.y, WB[15], eB1);

        unsigned long long vA = add2(eA0, eA1);
        unsigned long long vB = add2(eB0, eB1);
        float v0, v1, v2, v3;
        unpack2(vA, v0, v1);
        unpack2(vB, v2, v3);
        if (i != j) {
            a0 += fmaxf(v0, 0.f);
            a1 += fmaxf(v1, 0.f);
            a2 += fmaxf(v2, 0.f);
            a3 += fmaxf(v3, 0.f);
        }
    }

    float* dst = &g_aggp[blockIdx.y][j * ND];
    *(float2*)&dst[kA] = make_float2(a0, a1);
    *(float2*)&dst[kB] = make_float2(a2, a3);
}

// ---------------- K5: update MLP  n_out = relu([n, sum(aggp)] @ uW + ub) ----------------
// 256 threads, 2 nodes/block, thread = (nd, k).
__global__ __launch_bounds__(256) void k_upd(
    const float* __restrict__ nin,
    const float* __restrict__ uW, const float* __restrict__ ub,
    float* __restrict__ nout)
{
    __shared__ float xs[2][2 * ND];
    const int tid = threadIdx.x;
    const int nd = tid >> 7;
    const int k  = tid & 127;
    const int n0 = blockIdx.x * 2;

    {
        // fill xs[nd][0:128] = nin, xs[nd][128:256] = sum of partials
        int off = (n0 + nd) * ND + k;
        float s = g_aggp[0][off];
#pragma unroll
        for (int c = 1; c < NCH2; c++) s += g_aggp[c][off];
        xs[nd][k]      = nin[off];
        xs[nd][ND + k] = s;
    }
    __syncthreads();

    float acc = 0.f;
    for (int t = 0; t < 2 * ND; t++)
        acc += xs[nd][t] * uW[t * ND + k];
    nout[(n0 + nd) * ND + k] = fmaxf(acc + ub[k], 0.f);
}

// ---------------- K6: P = n@Wc1[:128],  Q = n@Wc1[128:] + bc1 ----------------
// 256 threads, 2 nodes/block: thread = (half P/Q, nd, k64).
__global__ __launch_bounds__(256) void k_pq(
    const float* __restrict__ nin,
    const float* __restrict__ Wc1, const float* __restrict__ bc1)
{
    __shared__ float xs[2][ND];
    const int tid = threadIdx.x;
    const int half = tid >> 7;            // 0 -> P, 1 -> Q
    const int nd = (tid >> 6) & 1;
    const int k  = tid & 63;
    const int n0 = blockIdx.x * 2;

    if (tid < 256) { /* all */ }
    if (tid < 2 * ND) xs[tid >> 7][tid & 127] = nin[n0 * ND + tid];
    __syncthreads();

    const float* Wcol = &Wc1[half * ND * 64];
    float acc = 0.f;
    for (int t = 0; t < ND; t++)
        acc += xs[nd][t] * Wcol[t * 64 + k];

    if (half) g_Q[(n0 + nd) * 64 + k] = acc + bc1[k];
    else      g_P[(n0 + nd) * 64 + k] = acc;
}

// ---------------- K7: pairwise scores (relu(P_i+Q_j) @ Wc2 -> sigmoid) ----------------
__global__ __launch_bounds__(256) void k_scores(
    const float* __restrict__ Wc2, const float* __restrict__ bc2,
    float* __restrict__ out)
{
    __shared__ float Ps[16][65], Qs[16][65], ws[64];
    const int tid = threadIdx.x;
    const int tx = tid & 15, ty = tid >> 4;
    const int j0 = blockIdx.x * 16, i0 = blockIdx.y * 16;

    for (int idx = tid; idx < 16 * 64; idx += 256) {
        int r = idx >> 6, c = idx & 63;
        Ps[r][c] = g_P[(i0 + r) * 64 + c];
        Qs[r][c] = g_Q[(j0 + r) * 64 + c];
    }
    if (tid < 64) ws[tid] = Wc2[tid];
    __syncthreads();

    float acc = 0.f;
#pragma unroll 8
    for (int t = 0; t < 64; t++)
        acc += fmaxf(Ps[ty][t] + Qs[tx][t], 0.f) * ws[t];
    acc += bc2[0];
    float s = 1.f / (1.f + expf(-acc));
    const int i = i0 + ty, j = j0 + tx;
    out[i * NN + j] = (i == j) ? 0.f : s;
}

// ---------------- launch ----------------
extern "C" void kernel_launch(void* const* d_in, const int* in_sizes, int n_in,
                              void* d_out, int out_size)
{
    const float* X   = (const float*)d_in[0];
    const float* pos = (const float*)d_in[1];
    const float* W1  = (const float*)d_in[2];
    const float* b1  = (const float*)d_in[3];
    const float* W2  = (const float*)d_in[4];
    const float* b2  = (const float*)d_in[5];
    const float* lng = (const float*)d_in[6];
    const float* lnb = (const float*)d_in[7];
    const float* We1 = (const float*)d_in[8];
    const float* be1 = (const float*)d_in[9];
    const float* We2 = (const float*)d_in[10];
    const float* be2 = (const float*)d_in[11];
    const float* mW1 = (const float*)d_in[12];
    const float* mb1 = (const float*)d_in[13];
    const float* uW1 = (const float*)d_in[14];
    const float* ub1 = (const float*)d_in[15];
    const float* mW2 = (const float*)d_in[16];
    const float* mb2 = (const float*)d_in[17];
    const float* uW2 = (const float*)d_in[18];
    const float* ub2 = (const float*)d_in[19];
    const float* Wc1 = (const float*)d_in[20];
    const float* bc1 = (const float*)d_in[21];
    const float* Wc2 = (const float*)d_in[22];
    const float* bc2 = (const float*)d_in[23];

    float* out   = (float*)d_out;
    float* out_n = out;             // [512*128] node features
    float* out_s = out + NN * ND;   // [512*512] scores

    float *pN = nullptr, *pN2 = nullptr;
    cudaGetSymbolAddress((void**)&pN,  g_n);
    cudaGetSymbolAddress((void**)&pN2, g_n2);

    // fused: node projector+LN (blocks 0..255) + edge encoder (blocks 256..767)
    k_pre<<<768, 256>>>(X, W1, b1, W2, b2, lng, lnb,
                        pos, We1, be1, We2, be2);

    // MPN layer 1
    k_ab<<<256, 256>>>(pN, mW1, mb1);
    k_agg<<<dim3(128, NCH2), 128>>>(mW1);
    k_upd<<<256, 256>>>(pN, uW1, ub1, pN2);

    // MPN layer 2 (final node features written straight into d_out)
    k_ab<<<256, 256>>>(pN2, mW2, mb2);
    k_agg<<<dim3(128, NCH2), 128>>>(mW2);
    k_upd<<<256, 256>>>(pN2, uW2, ub2, out_n);

    // classifier
    k_pq<<<256, 256>>>(out_n, Wc1, bc1);
    k_scores<<<dim3(32, 32), 256>>>(Wc2, bc2, out_s);
}

// round 8
// speedup vs baseline: 1.8528x; 1.0796x over previous
#include <cuda_runtime.h>
#include <cstdint>
#include <cstddef>

// Problem constants
#define NN 512
#define SD 256
#define ND 128
#define ED 16
#define CH 64               // i's per chunk in k_agg
#define NCH2 (NN / CH)      // 8 chunks
#define TT 32               // weight-tile rows for cp.async GEMMs

// ---------------- scratch (static device globals; no allocation) ----------------
__device__ float g_efd[NN * NN * 32];       // edge features, duplicated pairs: [j][i][t][2] (33.5 MB)
__device__ float g_n[NN * ND];              // node features after projector+LN
__device__ float g_n2[NN * ND];             // node features after MPN layer 1
__device__ float g_A[NN * ND];              // n @ mW_src
__device__ float g_B[NN * ND];              // n @ mW_dst + mb
__device__ float g_aggp[NCH2][NN * ND];     // partial aggregated messages (per i-chunk)
__device__ float g_P[NN * 64];              // n @ Wc1[:128]
__device__ float g_Q[NN * 64];              // n @ Wc1[128:] + bc1

// ---------------- packed f32x2 helpers (sm_103a FFMA2 path) ----------------
__device__ __forceinline__ unsigned long long pack2(float lo, float hi) {
    unsigned long long r;
    asm("mov.b64 %0, {%1, %2};" : "=l"(r) : "f"(lo), "f"(hi));
    return r;
}
__device__ __forceinline__ void unpack2(unsigned long long v, float& lo, float& hi) {
    asm("mov.b64 {%0, %1}, %2;" : "=f"(lo), "=f"(hi) : "l"(v));
}
__device__ __forceinline__ unsigned long long fma2(unsigned long long a,
                                                   unsigned long long b,
                                                   unsigned long long c) {
    unsigned long long d;
    asm("fma.rn.f32x2 %0, %1, %2, %3;" : "=l"(d) : "l"(a), "l"(b), "l"(c));
    return d;
}
__device__ __forceinline__ unsigned long long add2(unsigned long long a,
                                                   unsigned long long b) {
    unsigned long long d;
    asm("add.rn.f32x2 %0, %1, %2;" : "=l"(d) : "l"(a), "l"(b));
    return d;
}
__device__ __forceinline__ float tanh_fast(float x) {
    float y;
    asm("tanh.approx.f32 %0, %1;" : "=f"(y) : "f"(x));
    return y;
}

// ---------------- cp.async helpers ----------------
__device__ __forceinline__ uint32_t smem_u32(const void* p) {
    return (uint32_t)__cvta_generic_to_shared(p);
}
__device__ __forceinline__ void cp16(uint32_t s, const void* g) {
    asm volatile("cp.async.cg.shared.global [%0], [%1], 16;" :: "r"(s), "l"(g));
}
__device__ __forceinline__ void cp_commit() {
    asm volatile("cp.async.commit_group;" ::: "memory");
}
__device__ __forceinline__ void cp_wait0() {
    asm volatile("cp.async.wait_group 0;" ::: "memory");
}
__device__ __forceinline__ void cp_wait1() {
    asm volatile("cp.async.wait_group 1;" ::: "memory");
}

// stage one TT x C weight tile into smem buffer (NTHR threads, float4 chunks)
template<int C, int NTHR>
__device__ __forceinline__ void stage_tile(float* buf, const float* __restrict__ W,
                                           int tile, int tid) {
    const float* src = W + (size_t)tile * TT * C;
    uint32_t b = smem_u32(buf);
    constexpr int NV = TT * C / 4;          // float4s per tile
#pragma unroll
    for (int r = 0; r < NV / NTHR; r++) {
        int idx = tid + NTHR * r;
        cp16(b + idx * 16, src + idx * 4);
    }
    cp_commit();
}

// ---------------- K1 (fused): spatial projector+LN  |  edge encoder ----------------
// 256 threads. blocks [0,256): node MLP (NB=2, cp.async weight pipeline).
// blocks [256,768): edge encoder, j = bx-256.
__global__ __launch_bounds__(256) void k_pre(
    const float* __restrict__ X,
    const float* __restrict__ W1, const float* __restrict__ b1,
    const float* __restrict__ W2, const float* __restrict__ b2,
    const float* __restrict__ lng, const float* __restrict__ lnb,
    const float* __restrict__ pos,
    const float* __restrict__ We1, const float* __restrict__ be1,
    const float* __restrict__ We2, const float* __restrict__ be2)
{
    const int tid = threadIdx.x;
    if (blockIdx.x < 256) {
        __shared__ float xs[2][SD];
        __shared__ float h1[2][ND];
        __shared__ __align__(16) float wt[2][TT * ND];
        __shared__ float ssum[2][4], ssq[2][4];

        const int nd = tid >> 7;
        const int k  = tid & 127;
        const int n0 = blockIdx.x * 2;

        for (int idx = tid; idx < 2 * SD; idx += 256)
            xs[idx >> 8][idx & 255] = X[n0 * SD + idx];

        // ---- GEMM1: h1 = relu(xs @ W1 + b1), 8 tiles of 32x128 ----
        stage_tile<ND, 256>(wt[0], W1, 0, tid);
        stage_tile<ND, 256>(wt[1], W1, 1, tid);
        float acc = 0.f;
#pragma unroll
        for (int tile = 0; tile < 8; tile++) {
            const int buf = tile & 1;
            if (tile == 7) cp_wait0(); else cp_wait1();
            __syncthreads();
#pragma unroll
            for (int tt = 0; tt < TT; tt++)
                acc += xs[nd][tile * TT + tt] * wt[buf][tt * ND + k];
            if (tile + 2 < 8) {
                __syncthreads();
                stage_tile<ND, 256>(wt[buf], W1, tile + 2, tid);
            }
        }
        h1[nd][k] = fmaxf(acc + b1[k], 0.f);

        // ---- GEMM2: acc = h1 @ W2 + b2, 4 tiles of 32x128 ----
        stage_tile<ND, 256>(wt[0], W2, 0, tid);
        stage_tile<ND, 256>(wt[1], W2, 1, tid);
        acc = 0.f;
#pragma unroll
        for (int tile = 0; tile < 4; tile++) {
            const int buf = tile & 1;
            if (tile == 3) cp_wait0(); else cp_wait1();
            __syncthreads();          // also orders h1 writes before reads (tile 0)
#pragma unroll
            for (int tt = 0; tt < TT; tt++)
                acc += h1[nd][tile * TT + tt] * wt[buf][tt * ND + k];
            if (tile + 2 < 4) {
                __syncthreads();
                stage_tile<ND, 256>(wt[buf], W2, tile + 2, tid);
            }
        }
        acc += b2[k];

        // ---- LayerNorm ----
        const int w4 = (tid >> 5) & 3, lane = tid & 31;
        {
            float v = acc, v2 = v * v;
            for (int o = 16; o > 0; o >>= 1) {
                v  += __shfl_xor_sync(0xffffffffu, v,  o);
                v2 += __shfl_xor_sync(0xffffffffu, v2, o);
            }
            if (lane == 0) { ssum[nd][w4] = v; ssq[nd][w4] = v2; }
        }
        __syncthreads();
        float s = ssum[nd][0] + ssum[nd][1] + ssum[nd][2] + ssum[nd][3];
        float q = ssq[nd][0] + ssq[nd][1] + ssq[nd][2] + ssq[nd][3];
        float mu = s * (1.0f / ND);
        float var = q * (1.0f / ND) - mu * mu;
        float r = rsqrtf(var + 1e-5f);
        g_n[(n0 + nd) * ND + k] = (acc - mu) * r * lng[k] + lnb[k];
    } else {
        // ---- edge encoder: writes duplicated-pair layout ----
        __shared__ float w1s[64], b1s[16], w2s[256], b2s[16];
        if (tid < 64) w1s[tid] = We1[tid];
        if (tid < 256) { if (tid < 256) w2s[tid] = We2[tid]; }
        if (tid < 16) { b1s[tid] = be1[tid]; b2s[tid] = be2[tid]; }

        const int j = blockIdx.x - 256;
        const float pjx = pos[j * 2], pjy = pos[j * 2 + 1];
        __syncthreads();

        for (int i = tid; i < NN; i += 256) {
            float4* o4 = (float4*)&g_efd[((size_t)j * NN + i) * 32];
            if (i == j) {
                float4 z = make_float4(0.f, 0.f, 0.f, 0.f);
#pragma unroll
                for (int r = 0; r < 8; r++) o4[r] = z;
                continue;
            }
            const float pix = pos[i * 2], piy = pos[i * 2 + 1];
            const float dx = pjx - pix, dy = pjy - piy;
            const float dist = sqrtf(dx * dx + dy * dy);
            const float ang = atan2f(dy, dx);
            float h[16];
#pragma unroll
            for (int u = 0; u < 16; u++) {
                float a = pix * w1s[u] + piy * w1s[16 + u] + dist * w1s[32 + u]
                        + ang * w1s[48 + u] + b1s[u];
                h[u] = fmaxf(a, 0.f);
            }
            float o[16];
#pragma unroll
            for (int v = 0; v < 16; v++) {
                float a = b2s[v];
#pragma unroll
                for (int u = 0; u < 16; u++) a += h[u] * w2s[u * 16 + v];
                o[v] = tanh_fast(a);
            }
#pragma unroll
            for (int r = 0; r < 8; r++)
                o4[r] = make_float4(o[2 * r], o[2 * r], o[2 * r + 1], o[2 * r + 1]);
        }
    }
}

// ---------------- K3: A = n@mW_src,  B = n@mW_dst + mb ----------------
// 512 threads, NB=4 nodes/block, 128 blocks. cp.async weight pipeline over
// mW rows 0..255 (tiles 0-3 -> A, tiles 4-7 -> B).
__global__ __launch_bounds__(512) void k_ab(
    const float* __restrict__ nin,
    const float* __restrict__ mW, const float* __restrict__ mb)
{
    __shared__ float xs[4][ND];
    __shared__ __align__(16) float wt[2][TT * ND];
    const int tid = threadIdx.x;
    const int nd = tid >> 7;
    const int k  = tid & 127;
    const int n0 = blockIdx.x * 4;

    xs[nd][k] = nin[n0 * ND + tid];

    stage_tile<ND, 512>(wt[0], mW, 0, tid);
    stage_tile<ND, 512>(wt[1], mW, 1, tid);

    float accA = 0.f, accB = 0.f;
#pragma unroll
    for (int tile = 0; tile < 8; tile++) {
        const int buf = tile & 1;
        if (tile == 7) cp_wait0(); else cp_wait1();
        __syncthreads();
        if (tile < 4) {
#pragma unroll
            for (int tt = 0; tt < TT; tt++)
                accA += xs[nd][tile * TT + tt] * wt[buf][tt * ND + k];
        } else {
#pragma unroll
            for (int tt = 0; tt < TT; tt++)
                accB += xs[nd][(tile - 4) * TT + tt] * wt[buf][tt * ND + k];
        }
        if (tile + 2 < 8) {
            __syncthreads();
            stage_tile<ND, 512>(wt[buf], mW, tile + 2, tid);
        }
    }
    g_A[(n0 + nd) * ND + k] = accA;
    g_B[(n0 + nd) * ND + k] = accB + mb[k];
}

// ---------------- K4: fused ef-matvec + relu + segment-sum (partial) ----------------
// EXACT R3 version (proven). block = 128 threads = 4 warps, each warp one dst j;
// thread covers 4 features as two packed f32x2 chains. grid = (128, NCH2).
__global__ __launch_bounds__(128) void k_agg(const float* __restrict__ mW)
{
    __shared__ __align__(16) float efs[4][CH * 32];   // 4 warps * 8 KB = 32 KB

    const int grp  = threadIdx.x >> 5;
    const int lane = threadIdx.x & 31;
    const int j  = blockIdx.x * 4 + grp;
    const int i0 = blockIdx.y * CH;
    const int kA = 2 * lane;
    const int kB = 64 + 2 * lane;

    unsigned long long WA[ED], WB[ED];
#pragma unroll
    for (int t = 0; t < ED; t++) {
        float2 wa = *(const float2*)&mW[(2 * ND + t) * ND + kA];
        float2 wb = *(const float2*)&mW[(2 * ND + t) * ND + kB];
        WA[t] = pack2(wa.x, wa.y);
        WB[t] = pack2(wb.x, wb.y);
    }
    float2 ba = *(const float2*)&g_B[j * ND + kA];
    float2 bb = *(const float2*)&g_B[j * ND + kB];
    const unsigned long long BA = pack2(ba.x, ba.y);
    const unsigned long long BB = pack2(bb.x, bb.y);

    // stage this warp's CH i's of duplicated ef (8 KB) — coalesced copy
    {
        const float4* src = (const float4*)&g_efd[((size_t)j * NN + i0) * 32];
        float4* dst = (float4*)efs[grp];
#pragma unroll
        for (int r = 0; r < 16; r++)
            dst[lane + 32 * r] = src[lane + 32 * r];
    }
    __syncthreads();

    float a0 = 0.f, a1 = 0.f, a2 = 0.f, a3 = 0.f;
#pragma unroll 2
    for (int ii = 0; ii < CH; ii++) {
        const int i = i0 + ii;
        float2 aA = *(const float2*)&g_A[i * ND + kA];
        float2 aB = *(const float2*)&g_A[i * ND + kB];
        const ulonglong2* ep = (const ulonglong2*)&efs[grp][ii * 32];
        ulonglong2 q0 = ep[0], q1 = ep[1], q2 = ep[2], q3 = ep[3];
        ulonglong2 q4 = ep[4], q5 = ep[5], q6 = ep[6], q7 = ep[7];

        unsigned long long eA0 = BA, eA1 = pack2(aA.x, aA.y);
        unsigned long long eB0 = BB, eB1 = pack2(aB.x, aB.y);
        eA0 = fma2(q0.x, WA[0],  eA0);  eA1 = fma2(q0.y, WA[1],  eA1);
        eB0 = fma2(q0.x, WB[0],  eB0);  eB1 = fma2(q0.y, WB[1],  eB1);
        eA0 = fma2(q1.x, WA[2],  eA0);  eA1 = fma2(q1.y, WA[3],  eA1);
        eB0 = fma2(q1.x, WB[2],  eB0);  eB1 = fma2(q1.y, WB[3],  eB1);
        eA0 = fma2(q2.x, WA[4],  eA0);  eA1 = fma2(q2.y, WA[5],  eA1);
        eB0 = fma2(q2.x, WB[4],  eB0);  eB1 = fma2(q2.y, WB[5],  eB1);
        eA0 = fma2(q3.x, WA[6],  eA0);  eA1 = fma2(q3.y, WA[7],  eA1);
        eB0 = fma2(q3.x, WB[6],  eB0);  eB1 = fma2(q3.y, WB[7],  eB1);
        eA0 = fma2(q4.x, WA[8],  eA0);  eA1 = fma2(q4.y, WA[9],  eA1);
        eB0 = fma2(q4.x, WB[8],  eB0);  eB1 = fma2(q4.y, WB[9],  eB1);
        eA0 = fma2(q5.x, WA[10], eA0);  eA1 = fma2(q5.y, WA[11], eA1);
        eB0 = fma2(q5.x, WB[10], eB0);  eB1 = fma2(q5.y, WB[11], eB1);
        eA0 = fma2(q6.x, WA[12], eA0);  eA1 = fma2(q6.y, WA[13], eA1);
        eB0 = fma2(q6.x, WB[12], eB0);  eB1 = fma2(q6.y, WB[13], eB1);
        eA0 = fma2(q7.x, WA[14], eA0);  eA1 = fma2(q7.y, WA[15], eA1);
        eB0 = fma2(q7.x, WB[14], eB0);  eB1 = fma2(q7.y, WB[15], eB1);

        unsigned long long vA = add2(eA0, eA1);
        unsigned long long vB = add2(eB0, eB1);
        float v0, v1, v2, v3;
        unpack2(vA, v0, v1);
        unpack2(vB, v2, v3);
        if (i != j) {
            a0 += fmaxf(v0, 0.f);
            a1 += fmaxf(v1, 0.f);
            a2 += fmaxf(v2, 0.f);
            a3 += fmaxf(v3, 0.f);
        }
    }

    float* dst = &g_aggp[blockIdx.y][j * ND];
    *(float2*)&dst[kA] = make_float2(a0, a1);
    *(float2*)&dst[kB] = make_float2(a2, a3);
}

// ---------------- K5: update MLP  n_out = relu([n, sum(aggp)] @ uW + ub) ----------------
// 512 threads, NB=4 nodes/block, 128 blocks. cp.async pipeline over uW (8 tiles).
__global__ __launch_bounds__(512) void k_upd(
    const float* __restrict__ nin,
    const float* __restrict__ uW, const float* __restrict__ ub,
    float* __restrict__ nout)
{
    __shared__ float xs[4][2 * ND];
    __shared__ __align__(16) float wt[2][TT * ND];
    const int tid = threadIdx.x;
    const int nd = tid >> 7;
    const int k  = tid & 127;
    const int n0 = blockIdx.x * 4;

    {
        int off = (n0 + nd) * ND + k;
        float s = g_aggp[0][off];
#pragma unroll
        for (int c = 1; c < NCH2; c++) s += g_aggp[c][off];
        xs[nd][k]      = nin[off];
        xs[nd][ND + k] = s;
    }

    stage_tile<ND, 512>(wt[0], uW, 0, tid);
    stage_tile<ND, 512>(wt[1], uW, 1, tid);

    float acc = 0.f;
#pragma unroll
    for (int tile = 0; tile < 8; tile++) {
        const int buf = tile & 1;
        if (tile == 7) cp_wait0(); else cp_wait1();
        __syncthreads();
#pragma unroll
        for (int tt = 0; tt < TT; tt++)
            acc += xs[nd][tile * TT + tt] * wt[buf][tt * ND + k];
        if (tile + 2 < 8) {
            __syncthreads();
            stage_tile<ND, 512>(wt[buf], uW, tile + 2, tid);
        }
    }
    nout[(n0 + nd) * ND + k] = fmaxf(acc + ub[k], 0.f);
}

// ---------------- K6: P = n@Wc1[:128],  Q = n@Wc1[128:] + bc1 ----------------
// 256 threads, NB=4 nodes/block, 128 blocks. cp.async over Wc1 (8 tiles of 32x64);
// tiles 0-3 -> P, 4-7 -> Q. thread = (nd, k64).
__global__ __launch_bounds__(256) void k_pq(
    const float* __restrict__ nin,
    const float* __restrict__ Wc1, const float* __restrict__ bc1)
{
    __shared__ float xs[4][ND];
    __shared__ __align__(16) float wt[2][TT * 64];
    const int tid = threadIdx.x;
    const int nd = tid >> 6;
    const int k  = tid & 63;
    const int n0 = blockIdx.x * 4;

    for (int idx = tid; idx < 4 * ND; idx += 256)
        xs[idx >> 7][idx & 127] = nin[n0 * ND + idx];

    stage_tile<64, 256>(wt[0], Wc1, 0, tid);
    stage_tile<64, 256>(wt[1], Wc1, 1, tid);

    float accP = 0.f, accQ = 0.f;
#pragma unroll
    for (int tile = 0; tile < 8; tile++) {
        const int buf = tile & 1;
        if (tile == 7) cp_wait0(); else cp_wait1();
        __syncthreads();
        if (tile < 4) {
#pragma unroll
            for (int tt = 0; tt < TT; tt++)
                accP += xs[nd][tile * TT + tt] * wt[buf][tt * 64 + k];
        } else {
#pragma unroll
            for (int tt = 0; tt < TT; tt++)
                accQ += xs[nd][(tile - 4) * TT + tt] * wt[buf][tt * 64 + k];
        }
        if (tile + 2 < 8) {
            __syncthreads();
            stage_tile<64, 256>(wt[buf], Wc1, tile + 2, tid);
        }
    }
    g_P[(n0 + nd) * 64 + k] = accP;
    g_Q[(n0 + nd) * 64 + k] = accQ + bc1[k];
}

// ---------------- K7: pairwise scores (relu(P_i+Q_j) @ Wc2 -> sigmoid) ----------------
__global__ __launch_bounds__(256) void k_scores(
    const float* __restrict__ Wc2, const float* __restrict__ bc2,
    float* __restrict__ out)
{
    __shared__ float Ps[16][65], Qs[16][65], ws[64];
    const int tid = threadIdx.x;
    const int tx = tid & 15, ty = tid >> 4;
    const int j0 = blockIdx.x * 16, i0 = blockIdx.y * 16;

    for (int idx = tid; idx < 16 * 64; idx += 256) {
        int r = idx >> 6, c = idx & 63;
        Ps[r][c] = g_P[(i0 + r) * 64 + c];
        Qs[r][c] = g_Q[(j0 + r) * 64 + c];
    }
    if (tid < 64) ws[tid] = Wc2[tid];
    __syncthreads();

    float acc = 0.f;
#pragma unroll 8
    for (int t = 0; t < 64; t++)
        acc += fmaxf(Ps[ty][t] + Qs[tx][t], 0.f) * ws[t];
    acc += bc2[0];
    float s = 1.f / (1.f + expf(-acc));
    const int i = i0 + ty, j = j0 + tx;
    out[i * NN + j] = (i == j) ? 0.f : s;
}

// ---------------- launch ----------------
extern "C" void kernel_launch(void* const* d_in, const int* in_sizes, int n_in,
                              void* d_out, int out_size)
{
    const float* X   = (const float*)d_in[0];
    const float* pos = (const float*)d_in[1];
    const float* W1  = (const float*)d_in[2];
    const float* b1  = (const float*)d_in[3];
    const float* W2  = (const float*)d_in[4];
    const float* b2  = (const float*)d_in[5];
    const float* lng = (const float*)d_in[6];
    const float* lnb = (const float*)d_in[7];
    const float* We1 = (const float*)d_in[8];
    const float* be1 = (const float*)d_in[9];
    const float* We2 = (const float*)d_in[10];
    const float* be2 = (const float*)d_in[11];
    const float* mW1 = (const float*)d_in[12];
    const float* mb1 = (const float*)d_in[13];
    const float* uW1 = (const float*)d_in[14];
    const float* ub1 = (const float*)d_in[15];
    const float* mW2 = (const float*)d_in[16];
    const float* mb2 = (const float*)d_in[17];
    const float* uW2 = (const float*)d_in[18];
    const float* ub2 = (const float*)d_in[19];
    const float* Wc1 = (const float*)d_in[20];
    const float* bc1 = (const float*)d_in[21];
    const float* Wc2 = (const float*)d_in[22];
    const float* bc2 = (const float*)d_in[23];

    float* out   = (float*)d_out;
    float* out_n = out;             // [512*128] node features
    float* out_s = out + NN * ND;   // [512*512] scores

    float *pN = nullptr, *pN2 = nullptr;
    cudaGetSymbolAddress((void**)&pN,  g_n);
    cudaGetSymbolAddress((void**)&pN2, g_n2);

    // fused: node projector+LN (blocks 0..255) + edge encoder (blocks 256..767)
    k_pre<<<768, 256>>>(X, W1, b1, W2, b2, lng, lnb,
                        pos, We1, be1, We2, be2);

    // MPN layer 1
    k_ab<<<128, 512>>>(pN, mW1, mb1);
    k_agg<<<dim3(128, NCH2), 128>>>(mW1);
    k_upd<<<128, 512>>>(pN, uW1, ub1, pN2);

    // MPN layer 2 (final node features written straight into d_out)
    k_ab<<<128, 512>>>(pN2, mW2, mb2);
    k_agg<<<dim3(128, NCH2), 128>>>(mW2);
    k_upd<<<128, 512>>>(pN2, uW2, ub2, out_n);

    // classifier
    k_pq<<<128, 256>>>(out_n, Wc1, bc1);
    k_scores<<<dim3(32, 32), 256>>>(Wc2, bc2, out_s);
}

// round 9
// speedup vs baseline: 1.9203x; 1.0364x over previous
#include <cuda_runtime.h>
#include <cstdint>
#include <cstddef>

// Problem constants
#define NN 512
#define SD 256
#define ND 128
#define ED 16
#define CH 64               // i's per chunk in k_agg
#define NCH2 (NN / CH)      // 8 chunks
#define TT 32               // weight-tile rows for cp.async GEMMs

// ---------------- scratch (static device globals; no allocation) ----------------
__device__ float g_efd[NN * NN * 32];       // edge features, duplicated pairs: [j][i][t][2]
__device__ float g_n[NN * ND];              // node features after projector+LN
__device__ float g_n2[NN * ND];             // node features after MPN layer 1
__device__ float g_A[NN * ND];              // n @ mW_src
__device__ float g_B[NN * ND];              // n @ mW_dst + mb
__device__ float g_aggp[NCH2][NN * ND];     // partial aggregated messages (per i-chunk)
__device__ float g_P[NN * 64];              // n @ Wc1[:128]
__device__ float g_Q[NN * 64];              // n @ Wc1[128:] + bc1

// ---------------- packed f32x2 helpers ----------------
__device__ __forceinline__ unsigned long long pack2(float lo, float hi) {
    unsigned long long r;
    asm("mov.b64 %0, {%1, %2};" : "=l"(r) : "f"(lo), "f"(hi));
    return r;
}
__device__ __forceinline__ void unpack2(unsigned long long v, float& lo, float& hi) {
    asm("mov.b64 {%0, %1}, %2;" : "=f"(lo), "=f"(hi) : "l"(v));
}
__device__ __forceinline__ unsigned long long fma2(unsigned long long a,
                                                   unsigned long long b,
                                                   unsigned long long c) {
    unsigned long long d;
    asm("fma.rn.f32x2 %0, %1, %2, %3;" : "=l"(d) : "l"(a), "l"(b), "l"(c));
    return d;
}
__device__ __forceinline__ unsigned long long add2(unsigned long long a,
                                                   unsigned long long b) {
    unsigned long long d;
    asm("add.rn.f32x2 %0, %1, %2;" : "=l"(d) : "l"(a), "l"(b));
    return d;
}
__device__ __forceinline__ float tanh_fast(float x) {
    float y;
    asm("tanh.approx.f32 %0, %1;" : "=f"(y) : "f"(x));
    return y;
}

// ---------------- cp.async helpers ----------------
__device__ __forceinline__ uint32_t smem_u32(const void* p) {
    return (uint32_t)__cvta_generic_to_shared(p);
}
__device__ __forceinline__ void cp16(uint32_t s, const void* g) {
    asm volatile("cp.async.cg.shared.global [%0], [%1], 16;" :: "r"(s), "l"(g));
}
__device__ __forceinline__ void cp_commit() {
    asm volatile("cp.async.commit_group;" ::: "memory");
}
__device__ __forceinline__ void cp_wait0() {
    asm volatile("cp.async.wait_group 0;" ::: "memory");
}
__device__ __forceinline__ void cp_wait1() {
    asm volatile("cp.async.wait_group 1;" ::: "memory");
}

// stage one TT x C weight tile into smem buffer (NTHR threads, float4 chunks)
template<int C, int NTHR>
__device__ __forceinline__ void stage_tile(float* buf, const float* __restrict__ W,
                                           int tile, int tid) {
    const float* src = W + (size_t)tile * TT * C;
    uint32_t b = smem_u32(buf);
    constexpr int NV = TT * C / 4;          // float4s per tile
#pragma unroll
    for (int r = 0; r < NV / NTHR; r++) {
        int idx = tid + NTHR * r;
        cp16(b + idx * 16, src + idx * 4);
    }
    cp_commit();
}

// ---------------- K1 (fused): node projector+LN+AB1  |  edge encoder ----------------
// 256 threads. blocks [0,256): node path (NB=2). blocks [256,768): edge, j = bx-256.
__global__ __launch_bounds__(256) void k_pre(
    const float* __restrict__ X,
    const float* __restrict__ W1, const float* __restrict__ b1,
    const float* __restrict__ W2, const float* __restrict__ b2,
    const float* __restrict__ lng, const float* __restrict__ lnb,
    const float* __restrict__ pos,
    const float* __restrict__ We1, const float* __restrict__ be1,
    const float* __restrict__ We2, const float* __restrict__ be2,
    const float* __restrict__ mW, const float* __restrict__ mb)
{
    const int tid = threadIdx.x;
    if (blockIdx.x < 256) {
        __shared__ float xs[2][SD];
        __shared__ float h1[2][ND];
        __shared__ float xs2[2][ND];
        __shared__ __align__(16) float wt[2][TT * ND];
        __shared__ float ssum[2][4], ssq[2][4];

        const int nd = tid >> 7;
        const int k  = tid & 127;
        const int n0 = blockIdx.x * 2;

        for (int idx = tid; idx < 2 * SD; idx += 256)
            xs[idx >> 8][idx & 255] = X[n0 * SD + idx];

        // ---- GEMM1: h1 = relu(xs @ W1 + b1), 8 tiles of 32x128 ----
        stage_tile<ND, 256>(wt[0], W1, 0, tid);
        stage_tile<ND, 256>(wt[1], W1, 1, tid);
        float acc = 0.f;
#pragma unroll
        for (int tile = 0; tile < 8; tile++) {
            const int buf = tile & 1;
            if (tile == 7) cp_wait0(); else cp_wait1();
            __syncthreads();
#pragma unroll
            for (int tt = 0; tt < TT; tt++)
                acc += xs[nd][tile * TT + tt] * wt[buf][tt * ND + k];
            if (tile + 2 < 8) {
                __syncthreads();
                stage_tile<ND, 256>(wt[buf], W1, tile + 2, tid);
            }
        }
        h1[nd][k] = fmaxf(acc + b1[k], 0.f);

        // ---- GEMM2: acc = h1 @ W2 + b2, 4 tiles of 32x128 ----
        stage_tile<ND, 256>(wt[0], W2, 0, tid);
        stage_tile<ND, 256>(wt[1], W2, 1, tid);
        acc = 0.f;
#pragma unroll
        for (int tile = 0; tile < 4; tile++) {
            const int buf = tile & 1;
            if (tile == 3) cp_wait0(); else cp_wait1();
            __syncthreads();          // also orders h1 writes before reads (tile 0)
#pragma unroll
            for (int tt = 0; tt < TT; tt++)
                acc += h1[nd][tile * TT + tt] * wt[buf][tt * ND + k];
            if (tile + 2 < 4) {
                __syncthreads();
                stage_tile<ND, 256>(wt[buf], W2, tile + 2, tid);
            }
        }
        acc += b2[k];

        // wt[0] free (last read at tile 2, barrier passed): prefetch AB tile 0 now
        stage_tile<ND, 256>(wt[0], mW, 0, tid);

        // ---- LayerNorm ----
        const int w4 = (tid >> 5) & 3, lane = tid & 31;
        {
            float v = acc, v2 = v * v;
            for (int o = 16; o > 0; o >>= 1) {
                v  += __shfl_xor_sync(0xffffffffu, v,  o);
                v2 += __shfl_xor_sync(0xffffffffu, v2, o);
            }
            if (lane == 0) { ssum[nd][w4] = v; ssq[nd][w4] = v2; }
        }
        __syncthreads();              // ssum ready; also all reads of wt[1] done
        stage_tile<ND, 256>(wt[1], mW, 1, tid);
        float s = ssum[nd][0] + ssum[nd][1] + ssum[nd][2] + ssum[nd][3];
        float q = ssq[nd][0] + ssq[nd][1] + ssq[nd][2] + ssq[nd][3];
        float mu = s * (1.0f / ND);
        float var = q * (1.0f / ND) - mu * mu;
        float r = rsqrtf(var + 1e-5f);
        float nval = (acc - mu) * r * lng[k] + lnb[k];
        g_n[(n0 + nd) * ND + k] = nval;
        xs2[nd][k] = nval;

        // ---- AB1: A = n@mW[:128], B = n@mW[128:256] + mb, 8 tiles ----
        float accA = 0.f, accB = 0.f;
#pragma unroll
        for (int tile = 0; tile < 8; tile++) {
            const int buf = tile & 1;
            if (tile == 7) cp_wait0(); else cp_wait1();
            __syncthreads();          // tile 0: also publishes xs2
            if (tile < 4) {
#pragma unroll
                for (int tt = 0; tt < TT; tt++)
                    accA += xs2[nd][tile * TT + tt] * wt[buf][tt * ND + k];
            } else {
#pragma unroll
                for (int tt = 0; tt < TT; tt++)
                    accB += xs2[nd][(tile - 4) * TT + tt] * wt[buf][tt * ND + k];
            }
            if (tile + 2 < 8) {
                __syncthreads();
                stage_tile<ND, 256>(wt[buf], mW, tile + 2, tid);
            }
        }
        g_A[(n0 + nd) * ND + k] = accA;
        g_B[(n0 + nd) * ND + k] = accB + mb[k];
    } else {
        // ---- edge encoder: writes duplicated-pair layout ----
        __shared__ float w1s[64], b1s[16], w2s[256], b2s[16];
        if (tid < 64) w1s[tid] = We1[tid];
        if (tid < 256) w2s[tid] = We2[tid];
        if (tid < 16) { b1s[tid] = be1[tid]; b2s[tid] = be2[tid]; }

        const int j = blockIdx.x - 256;
        const float pjx = pos[j * 2], pjy = pos[j * 2 + 1];
        __syncthreads();

        for (int i = tid; i < NN; i += 256) {
            float4* o4 = (float4*)&g_efd[((size_t)j * NN + i) * 32];
            if (i == j) {
                float4 z = make_float4(0.f, 0.f, 0.f, 0.f);
#pragma unroll
                for (int r = 0; r < 8; r++) o4[r] = z;
                continue;
            }
            const float pix = pos[i * 2], piy = pos[i * 2 + 1];
            const float dx = pjx - pix, dy = pjy - piy;
            const float dist = sqrtf(dx * dx + dy * dy);
            const float ang = atan2f(dy, dx);
            float h[16];
#pragma unroll
            for (int u = 0; u < 16; u++) {
                float a = pix * w1s[u] + piy * w1s[16 + u] + dist * w1s[32 + u]
                        + ang * w1s[48 + u] + b1s[u];
                h[u] = fmaxf(a, 0.f);
            }
            float o[16];
#pragma unroll
            for (int v = 0; v < 16; v++) {
                float a = b2s[v];
#pragma unroll
                for (int u = 0; u < 16; u++) a += h[u] * w2s[u * 16 + v];
                o[v] = tanh_fast(a);
            }
#pragma unroll
            for (int r = 0; r < 8; r++)
                o4[r] = make_float4(o[2 * r], o[2 * r], o[2 * r + 1], o[2 * r + 1]);
        }
    }
}

// ---------------- K4: fused ef-matvec + relu + segment-sum (partial) ----------------
// EXACT proven version. grid = (128, NCH2), 128 threads.
__global__ __launch_bounds__(128) void k_agg(const float* __restrict__ mW)
{
    __shared__ __align__(16) float efs[4][CH * 32];

    const int grp  = threadIdx.x >> 5;
    const int lane = threadIdx.x & 31;
    const int j  = blockIdx.x * 4 + grp;
    const int i0 = blockIdx.y * CH;
    const int kA = 2 * lane;
    const int kB = 64 + 2 * lane;

    unsigned long long WA[ED], WB[ED];
#pragma unroll
    for (int t = 0; t < ED; t++) {
        float2 wa = *(const float2*)&mW[(2 * ND + t) * ND + kA];
        float2 wb = *(const float2*)&mW[(2 * ND + t) * ND + kB];
        WA[t] = pack2(wa.x, wa.y);
        WB[t] = pack2(wb.x, wb.y);
    }
    float2 ba = *(const float2*)&g_B[j * ND + kA];
    float2 bb = *(const float2*)&g_B[j * ND + kB];
    const unsigned long long BA = pack2(ba.x, ba.y);
    const unsigned long long BB = pack2(bb.x, bb.y);

    {
        const float4* src = (const float4*)&g_efd[((size_t)j * NN + i0) * 32];
        float4* dst = (float4*)efs[grp];
#pragma unroll
        for (int r = 0; r < 16; r++)
            dst[lane + 32 * r] = src[lane + 32 * r];
    }
    __syncthreads();

    float a0 = 0.f, a1 = 0.f, a2 = 0.f, a3 = 0.f;
#pragma unroll 2
    for (int ii = 0; ii < CH; ii++) {
        const int i = i0 + ii;
        float2 aA = *(const float2*)&g_A[i * ND + kA];
        float2 aB = *(const float2*)&g_A[i * ND + kB];
        const ulonglong2* ep = (const ulonglong2*)&efs[grp][ii * 32];
        ulonglong2 q0 = ep[0], q1 = ep[1], q2 = ep[2], q3 = ep[3];
        ulonglong2 q4 = ep[4], q5 = ep[5], q6 = ep[6], q7 = ep[7];

        unsigned long long eA0 = BA, eA1 = pack2(aA.x, aA.y);
        unsigned long long eB0 = BB, eB1 = pack2(aB.x, aB.y);
        eA0 = fma2(q0.x, WA[0],  eA0);  eA1 = fma2(q0.y, WA[1],  eA1);
        eB0 = fma2(q0.x, WB[0],  eB0);  eB1 = fma2(q0.y, WB[1],  eB1);
        eA0 = fma2(q1.x, WA[2],  eA0);  eA1 = fma2(q1.y, WA[3],  eA1);
        eB0 = fma2(q1.x, WB[2],  eB0);  eB1 = fma2(q1.y, WB[3],  eB1);
        eA0 = fma2(q2.x, WA[4],  eA0);  eA1 = fma2(q2.y, WA[5],  eA1);
        eB0 = fma2(q2.x, WB[4],  eB0);  eB1 = fma2(q2.y, WB[5],  eB1);
        eA0 = fma2(q3.x, WA[6],  eA0);  eA1 = fma2(q3.y, WA[7],  eA1);
        eB0 = fma2(q3.x, WB[6],  eB0);  eB1 = fma2(q3.y, WB[7],  eB1);
        eA0 = fma2(q4.x, WA[8],  eA0);  eA1 = fma2(q4.y, WA[9],  eA1);
        eB0 = fma2(q4.x, WB[8],  eB0);  eB1 = fma2(q4.y, WB[9],  eB1);
        eA0 = fma2(q5.x, WA[10], eA0);  eA1 = fma2(q5.y, WA[11], eA1);
        eB0 = fma2(q5.x, WB[10], eB0);  eB1 = fma2(q5.y, WB[11], eB1);
        eA0 = fma2(q6.x, WA[12], eA0);  eA1 = fma2(q6.y, WA[13], eA1);
        eB0 = fma2(q6.x, WB[12], eB0);  eB1 = fma2(q6.y, WB[13], eB1);
        eA0 = fma2(q7.x, WA[14], eA0);  eA1 = fma2(q7.y, WA[15], eA1);
        eB0 = fma2(q7.x, WB[14], eB0);  eB1 = fma2(q7.y, WB[15], eB1);

        unsigned long long vA = add2(eA0, eA1);
        unsigned long long vB = add2(eB0, eB1);
        float v0, v1, v2, v3;
        unpack2(vA, v0, v1);
        unpack2(vB, v2, v3);
        if (i != j) {
            a0 += fmaxf(v0, 0.f);
            a1 += fmaxf(v1, 0.f);
            a2 += fmaxf(v2, 0.f);
            a3 += fmaxf(v3, 0.f);
        }
    }

    float* dst = &g_aggp[blockIdx.y][j * ND];
    *(float2*)&dst[kA] = make_float2(a0, a1);
    *(float2*)&dst[kB] = make_float2(a2, a3);
}

// ---------------- K5a: upd (layer 1) fused with AB2 ----------------
// 512 threads, NB=4 nodes/block, 128 blocks.
__global__ __launch_bounds__(512) void k_upd_ab(
    const float* __restrict__ nin,
    const float* __restrict__ uW, const float* __restrict__ ub,
    float* __restrict__ nout,
    const float* __restrict__ mW, const float* __restrict__ mb)
{
    __shared__ float xs[4][2 * ND];
    __shared__ float xs2[4][ND];
    __shared__ __align__(16) float wt[2][TT * ND];
    const int tid = threadIdx.x;
    const int nd = tid >> 7;
    const int k  = tid & 127;
    const int n0 = blockIdx.x * 4;

    {
        int off = (n0 + nd) * ND + k;
        float s = g_aggp[0][off];
#pragma unroll
        for (int c = 1; c < NCH2; c++) s += g_aggp[c][off];
        xs[nd][k]      = nin[off];
        xs[nd][ND + k] = s;
    }

    stage_tile<ND, 512>(wt[0], uW, 0, tid);
    stage_tile<ND, 512>(wt[1], uW, 1, tid);

    float acc = 0.f;
#pragma unroll
    for (int tile = 0; tile < 8; tile++) {
        const int buf = tile & 1;
        if (tile == 7) cp_wait0(); else cp_wait1();
        __syncthreads();
#pragma unroll
        for (int tt = 0; tt < TT; tt++)
            acc += xs[nd][tile * TT + tt] * wt[buf][tt * ND + k];
        if (tile + 2 < 8) {
            __syncthreads();
            stage_tile<ND, 512>(wt[buf], uW, tile + 2, tid);
        }
    }
    float nval = fmaxf(acc + ub[k], 0.f);
    nout[(n0 + nd) * ND + k] = nval;
    xs2[nd][k] = nval;

    // wt[0] free (last read tile 6, barrier passed at tile 7's top)
    stage_tile<ND, 512>(wt[0], mW, 0, tid);
    __syncthreads();                       // all done reading wt[1]; xs2 published
    stage_tile<ND, 512>(wt[1], mW, 1, tid);

    // ---- AB2 ----
    float accA = 0.f, accB = 0.f;
#pragma unroll
    for (int tile = 0; tile < 8; tile++) {
        const int buf = tile & 1;
        if (tile == 7) cp_wait0(); else cp_wait1();
        __syncthreads();
        if (tile < 4) {
#pragma unroll
            for (int tt = 0; tt < TT; tt++)
                accA += xs2[nd][tile * TT + tt] * wt[buf][tt * ND + k];
        } else {
#pragma unroll
            for (int tt = 0; tt < TT; tt++)
                accB += xs2[nd][(tile - 4) * TT + tt] * wt[buf][tt * ND + k];
        }
        if (tile + 2 < 8) {
            __syncthreads();
            stage_tile<ND, 512>(wt[buf], mW, tile + 2, tid);
        }
    }
    g_A[(n0 + nd) * ND + k] = accA;
    g_B[(n0 + nd) * ND + k] = accB + mb[k];
}

// ---------------- K5b: upd (layer 2) fused with P/Q classifier GEMM ----------------
// 512 threads, NB=4 nodes/block, 128 blocks. P/Q tiles staged as pairs so both
// thread-halves stay busy: phase p stages Wc1 rows [32p,32p+32) (P) and
// [128+32p, 128+32p+32) (Q) into one 16KB buffer.
__global__ __launch_bounds__(512) void k_upd_pq(
    const float* __restrict__ nin,
    const float* __restrict__ uW, const float* __restrict__ ub,
    float* __restrict__ nout,
    const float* __restrict__ Wc1, const float* __restrict__ bc1)
{
    __shared__ float xs[4][2 * ND];
    __shared__ float xs2[4][ND];
    __shared__ __align__(16) float wt[2][TT * ND];   // reused as [2][2][TT*64] for PQ
    const int tid = threadIdx.x;
    const int nd = tid >> 7;
    const int k  = tid & 127;
    const int n0 = blockIdx.x * 4;

    {
        int off = (n0 + nd) * ND + k;
        float s = g_aggp[0][off];
#pragma unroll
        for (int c = 1; c < NCH2; c++) s += g_aggp[c][off];
        xs[nd][k]      = nin[off];
        xs[nd][ND + k] = s;
    }

    stage_tile<ND, 512>(wt[0], uW, 0, tid);
    stage_tile<ND, 512>(wt[1], uW, 1, tid);

    float acc = 0.f;
#pragma unroll
    for (int tile = 0; tile < 8; tile++) {
        const int buf = tile & 1;
        if (tile == 7) cp_wait0(); else cp_wait1();
        __syncthreads();
#pragma unroll
        for (int tt = 0; tt < TT; tt++)
            acc += xs[nd][tile * TT + tt] * wt[buf][tt * ND + k];
        if (tile + 2 < 8) {
            __syncthreads();
            stage_tile<ND, 512>(wt[buf], uW, tile + 2, tid);
        }
    }
    float nval = fmaxf(acc + ub[k], 0.f);
    nout[(n0 + nd) * ND + k] = nval;
    xs2[nd][k] = nval;

    // ---- PQ: stage P-tile + Q-tile pairs (16KB each phase, 4 phases) ----
    // phase buffer layout: floats [0,2048) = P rows, [2048,4096) = Q rows
    {
        // wt[0] free; stage phase 0
        uint32_t b0 = smem_u32(wt[0]);
        cp16(b0 + tid * 16, Wc1 + 0 * TT * 64 + tid * 4);                 // P rows 0-31
        cp16(b0 + 8192 + tid * 16, Wc1 + (128 + 0 * TT) * 64 + tid * 4);  // Q rows 128-159
        cp_commit();
    }
    __syncthreads();                       // wt[1] free; xs2 published
    {
        uint32_t b1 = smem_u32(wt[1]);
        cp16(b1 + tid * 16, Wc1 + 1 * TT * 64 + tid * 4);
        cp16(b1 + 8192 + tid * 16, Wc1 + (128 + 1 * TT) * 64 + tid * 4);
        cp_commit();
    }

    const int half = (k >> 6);             // 0 -> P, 1 -> Q
    const int k64  = k & 63;
    float accPQ = 0.f;
#pragma unroll
    for (int phase = 0; phase < 4; phase++) {
        const int buf = phase & 1;
        if (phase == 3) cp_wait0(); else cp_wait1();
        __syncthreads();
        const float* w = &wt[buf][half * 2048];
#pragma unroll
        for (int tt = 0; tt < TT; tt++)
            accPQ += xs2[nd][phase * TT + tt] * w[tt * 64 + k64];
        if (phase + 2 < 4) {
            __syncthreads();
            uint32_t b = smem_u32(wt[buf]);
            cp16(b + tid * 16, Wc1 + (phase + 2) * TT * 64 + tid * 4);
            cp16(b + 8192 + tid * 16, Wc1 + (128 + (phase + 2) * TT) * 64 + tid * 4);
            cp_commit();
        }
    }
    if (half) g_Q[(n0 + nd) * 64 + k64] = accPQ + bc1[k64];
    else      g_P[(n0 + nd) * 64 + k64] = accPQ;
}

// ---------------- K7: pairwise scores (relu(P_i+Q_j) @ Wc2 -> sigmoid) ----------------
__global__ __launch_bounds__(256) void k_scores(
    const float* __restrict__ Wc2, const float* __restrict__ bc2,
    float* __restrict__ out)
{
    __shared__ float Ps[16][65], Qs[16][65], ws[64];
    const int tid = threadIdx.x;
    const int tx = tid & 15, ty = tid >> 4;
    const int j0 = blockIdx.x * 16, i0 = blockIdx.y * 16;

    for (int idx = tid; idx < 16 * 64; idx += 256) {
        int r = idx >> 6, c = idx & 63;
        Ps[r][c] = g_P[(i0 + r) * 64 + c];
        Qs[r][c] = g_Q[(j0 + r) * 64 + c];
    }
    if (tid < 64) ws[tid] = Wc2[tid];
    __syncthreads();

    float acc = 0.f;
#pragma unroll 8
    for (int t = 0; t < 64; t++)
        acc += fmaxf(Ps[ty][t] + Qs[tx][t], 0.f) * ws[t];
    acc += bc2[0];
    float s = 1.f / (1.f + expf(-acc));
    const int i = i0 + ty, j = j0 + tx;
    out[i * NN + j] = (i == j) ? 0.f : s;
}

// ---------------- launch ----------------
extern "C" void kernel_launch(void* const* d_in, const int* in_sizes, int n_in,
                              void* d_out, int out_size)
{
    const float* X   = (const float*)d_in[0];
    const float* pos = (const float*)d_in[1];
    const float* W1  = (const float*)d_in[2];
    const float* b1  = (const float*)d_in[3];
    const float* W2  = (const float*)d_in[4];
    const float* b2  = (const float*)d_in[5];
    const float* lng = (const float*)d_in[6];
    const float* lnb = (const float*)d_in[7];
    const float* We1 = (const float*)d_in[8];
    const float* be1 = (const float*)d_in[9];
    const float* We2 = (const float*)d_in[10];
    const float* be2 = (const float*)d_in[11];
    const float* mW1 = (const float*)d_in[12];
    const float* mb1 = (const float*)d_in[13];
    const float* uW1 = (const float*)d_in[14];
    const float* ub1 = (const float*)d_in[15];
    const float* mW2 = (const float*)d_in[16];
    const float* mb2 = (const float*)d_in[17];
    const float* uW2 = (const float*)d_in[18];
    const float* ub2 = (const float*)d_in[19];
    const float* Wc1 = (const float*)d_in[20];
    const float* bc1 = (const float*)d_in[21];
    const float* Wc2 = (const float*)d_in[22];
    const float* bc2 = (const float*)d_in[23];

    float* out   = (float*)d_out;
    float* out_n = out;             // [512*128] node features
    float* out_s = out + NN * ND;   // [512*512] scores

    float *pN = nullptr, *pN2 = nullptr;
    cudaGetSymbolAddress((void**)&pN,  g_n);
    cudaGetSymbolAddress((void**)&pN2, g_n2);

    // node projector+LN+AB1 (blocks 0..255) + edge encoder (blocks 256..767)
    k_pre<<<768, 256>>>(X, W1, b1, W2, b2, lng, lnb,
                        pos, We1, be1, We2, be2, mW1, mb1);

    // MPN layer 1 (agg) then fused update+AB2
    k_agg<<<dim3(128, NCH2), 128>>>(mW1);
    k_upd_ab<<<128, 512>>>(pN, uW1, ub1, pN2, mW2, mb2);

    // MPN layer 2 (agg) then fused update+PQ (final node features -> d_out)
    k_agg<<<dim3(128, NCH2), 128>>>(mW2);
    k_upd_pq<<<128, 512>>>(pN2, uW2, ub2, out_n, Wc1, bc1);

    // pairwise scores
    k_scores<<<dim3(32, 32), 256>>>(Wc2, bc2, out_s);
}